// round 2
// baseline (speedup 1.0000x reference)
#include <cuda_runtime.h>

#define MAXN 50048      // max nodes, padded
#define FEAT 64

// ---- static device scratch (no allocations allowed) ----
__device__ float4 g_h[MAXN * 16];      // layer-1 scatter source: x * norm_out
__device__ float4 g_y[MAXN * 16];      // layer-2 scatter source: tanh(conv1)*norm_out
__device__ float4 g_agg1[MAXN * 16];   // conv1 aggregation
__device__ float4 g_agg2[MAXN * 16];   // conv2 aggregation
__device__ float  g_no[MAXN];          // D_src^{-1/2}
__device__ float  g_ni[MAXN];          // D_dst^{-1/2}
__device__ float  g_dego[MAXN];
__device__ float  g_degi[MAXN];

// ---- zero accumulators + degree counters (replay-safe) ----
__global__ void k_zero() {
    int i = blockIdx.x * blockDim.x + threadIdx.x;
    float4 z = make_float4(0.f, 0.f, 0.f, 0.f);
    if (i < MAXN * 16) { g_agg1[i] = z; g_agg2[i] = z; }
    if (i < MAXN)      { g_dego[i] = 0.f; g_degi[i] = 0.f; }
}

// ---- degree counting: exact integer accumulation in float, order-independent ----
__global__ void k_deg(const int* __restrict__ src, const int* __restrict__ dst, int E) {
    int e = blockIdx.x * blockDim.x + threadIdx.x;
    if (e >= E) return;
    atomicAdd(&g_dego[src[e]], 1.0f);
    atomicAdd(&g_degi[dst[e]], 1.0f);
}

__global__ void k_norm(int N) {
    int n = blockIdx.x * blockDim.x + threadIdx.x;
    if (n >= N) return;
    float d0 = g_dego[n], d1 = g_degi[n];
    g_no[n] = d0 > 0.f ? rsqrtf(d0) : 0.f;
    g_ni[n] = d1 > 0.f ? rsqrtf(d1) : 0.f;
}

// ---- h = x * norm_out, coalesced float4 ----
__global__ void k_scale(const float4* __restrict__ x, int N) {
    int i = blockIdx.x * blockDim.x + threadIdx.x;
    if (i >= N * 16) return;
    float s = g_no[i >> 4];
    float4 v = x[i];
    v.x *= s; v.y *= s; v.z *= s; v.w *= s;
    g_h[i] = v;
}

// ---- edge scatter: agg[dst] += h[src], vector RED (one float4 per thread) ----
__global__ void k_scatter(const int* __restrict__ src, const int* __restrict__ dst,
                          int E, int layer) {
    int idx = blockIdx.x * blockDim.x + threadIdx.x;
    if (idx >= E * 16) return;
    int e = idx >> 4, k = idx & 15;
    int s = __ldg(src + e);
    int d = __ldg(dst + e);
    const float4* __restrict__ hp = layer ? g_y : g_h;
    float4*                    ap = layer ? g_agg2 : g_agg1;
    float4 v = __ldg(hp + s * 16 + k);
    float* p = reinterpret_cast<float*>(ap + d * 16 + k);
    asm volatile("red.global.add.v4.f32 [%0], {%1, %2, %3, %4};"
                 :: "l"(p), "f"(v.x), "f"(v.y), "f"(v.z), "f"(v.w) : "memory");
}

// ---- 64-wide GEMM: out = f((agg * norm_in) @ W + b)
// MODE 0: f = tanh, then * norm_out  -> g_y  (conv1 epilogue + conv2 prologue)
// MODE 1: f = identity, fused @J^T column rotation+sign -> d_out
template<int MODE>
__global__ void __launch_bounds__(256, 4)
k_gemm(const float* __restrict__ W, const float* __restrict__ bias,
       float* __restrict__ dout, int N) {
    __shared__ float  As[64][65];      // padded: kills bank conflicts on column reads
    __shared__ float4 Ws[64 * 16];     // W row-major as float4
    int t  = threadIdx.x;              // 256 threads
    int r0 = blockIdx.x * 64;
    const float4* __restrict__ A = (MODE == 0) ? g_agg1 : g_agg2;
    const float4* W4 = reinterpret_cast<const float4*>(W);

#pragma unroll
    for (int i = 0; i < 4; i++) Ws[t + 256 * i] = W4[t + 256 * i];
#pragma unroll
    for (int i = 0; i < 4; i++) {
        int f   = t + 256 * i;         // float4 index within 64x16 tile
        int row = f >> 4, c4 = f & 15;
        int gr  = r0 + row;
        float4 v = make_float4(0.f, 0.f, 0.f, 0.f);
        if (gr < N) {
            v = A[gr * 16 + c4];
            float ni = g_ni[gr];
            v.x *= ni; v.y *= ni; v.z *= ni; v.w *= ni;
        }
        As[row][c4 * 4 + 0] = v.x; As[row][c4 * 4 + 1] = v.y;
        As[row][c4 * 4 + 2] = v.z; As[row][c4 * 4 + 3] = v.w;
    }
    __syncthreads();

    int rr = (t >> 4) * 4;             // 4 rows per thread
    int cc = (t & 15) * 4;             // 4 cols per thread
    float acc[4][4];
#pragma unroll
    for (int i = 0; i < 4; i++)
#pragma unroll
        for (int j = 0; j < 4; j++) acc[i][j] = 0.f;

#pragma unroll
    for (int k = 0; k < 64; k++) {
        float4 w = Ws[k * 16 + (t & 15)];
#pragma unroll
        for (int i = 0; i < 4; i++) {
            float a = As[rr + i][k];
            acc[i][0] += a * w.x; acc[i][1] += a * w.y;
            acc[i][2] += a * w.z; acc[i][3] += a * w.w;
        }
    }

    float b0 = bias[cc], b1 = bias[cc + 1], b2 = bias[cc + 2], b3 = bias[cc + 3];
#pragma unroll
    for (int i = 0; i < 4; i++) {
        int gr = r0 + rr + i;
        if (gr >= N) continue;
        float v0 = acc[i][0] + b0, v1 = acc[i][1] + b1;
        float v2 = acc[i][2] + b2, v3 = acc[i][3] + b3;
        if (MODE == 0) {
            float no = g_no[gr];
            g_y[gr * 16 + (cc >> 2)] =
                make_float4(tanhf(v0) * no, tanhf(v1) * no,
                            tanhf(v2) * no, tanhf(v3) * no);
        } else {
            // out[:, c] = y2[:, c+32] for c<32 ; out[:, c] = -y2[:, c-32] for c>=32
            // => column j of y2 goes to ((j+32)&63), negated iff j<32.
            int   oc  = (cc + 32) & 63;
            float sgn = (cc < 32) ? -1.f : 1.f;
            reinterpret_cast<float4*>(dout)[gr * 16 + (oc >> 2)] =
                make_float4(sgn * v0, sgn * v1, sgn * v2, sgn * v3);
        }
    }
}

extern "C" void kernel_launch(void* const* d_in, const int* in_sizes, int n_in,
                              void* d_out, int out_size) {
    const float* x   = (const float*)d_in[0];
    const int*   src = (const int*)  d_in[1];
    const int*   dst = (const int*)  d_in[2];
    const float* W1  = (const float*)d_in[3];
    const float* b1  = (const float*)d_in[4];
    const float* W2  = (const float*)d_in[5];
    const float* b2  = (const float*)d_in[6];

    int N = in_sizes[0] / FEAT;   // 50000
    int E = in_sizes[1];          // 800000
    const int T = 256;

    k_zero<<<(MAXN * 16 + T - 1) / T, T>>>();
    k_deg<<<(E + T - 1) / T, T>>>(src, dst, E);
    k_norm<<<(N + T - 1) / T, T>>>(N);
    k_scale<<<(N * 16 + T - 1) / T, T>>>((const float4*)x, N);

    int sBlocks = (E * 16 + T - 1) / T;
    int gBlocks = (N + 63) / 64;

    k_scatter<<<sBlocks, T>>>(src, dst, E, 0);
    k_gemm<0><<<gBlocks, 256>>>(W1, b1, nullptr, N);
    k_scatter<<<sBlocks, T>>>(src, dst, E, 1);
    k_gemm<1><<<gBlocks, 256>>>(W2, b2, (float*)d_out, N);
}

// round 3
// speedup vs baseline: 1.3072x; 1.3072x over previous
#include <cuda_runtime.h>

#define MAXN 50048
#define MAXE 800000
#define FEAT 64

// ---- static device scratch ----
__device__ float4 g_h[MAXN * 16];      // layer-1 gather source: x * norm_out
__device__ float4 g_y[MAXN * 16];      // layer-2 gather source: tanh(conv1)*norm_out
__device__ float4 g_agg1[MAXN * 16];
__device__ float4 g_agg2[MAXN * 16];
__device__ float  g_no[MAXN];          // D_src^{-1/2}
__device__ float  g_ni[MAXN];          // D_dst^{-1/2}
__device__ int    g_dego_i[MAXN];
__device__ int    g_degi_i[MAXN];
__device__ int    g_rowptr[MAXN];
__device__ int    g_cursor[MAXN];
__device__ int    g_part[128];
__device__ int    g_eidx[MAXE];        // CSR-by-dst: src ids

// ---- zero int degree counters only (no more 25.6MB agg zeroing) ----
__global__ void k_zero(int N) {
    int i = blockIdx.x * blockDim.x + threadIdx.x;
    if (i < N) { g_dego_i[i] = 0; g_degi_i[i] = 0; }
}

__global__ void k_deg(const int* __restrict__ src, const int* __restrict__ dst, int E) {
    int e = blockIdx.x * blockDim.x + threadIdx.x;
    if (e >= E) return;
    atomicAdd(&g_dego_i[src[e]], 1);
    atomicAdd(&g_degi_i[dst[e]], 1);
}

// ---- 3-phase exclusive scan of degi -> rowptr (chunk = 1024) ----
__global__ void k_scan_part(int N) {
    int i = blockIdx.x * 1024 + threadIdx.x;
    int v = (i < N) ? g_degi_i[i] : 0;
    __shared__ int sh[32];
    int w = threadIdx.x >> 5, l = threadIdx.x & 31;
#pragma unroll
    for (int o = 16; o; o >>= 1) v += __shfl_down_sync(~0u, v, o);
    if (l == 0) sh[w] = v;
    __syncthreads();
    if (w == 0) {
        int s = sh[l];
#pragma unroll
        for (int o = 16; o; o >>= 1) s += __shfl_down_sync(~0u, s, o);
        if (l == 0) g_part[blockIdx.x] = s;
    }
}

__global__ void k_scan_mid(int NB) {
    if (threadIdx.x == 0) {
        int s = 0;
        for (int b = 0; b < NB; b++) { int t = g_part[b]; g_part[b] = s; s += t; }
    }
}

// exclusive scan within chunk + block offset; also norms + cursor init
__global__ void k_scan_final(int N) {
    int i = blockIdx.x * 1024 + threadIdx.x;
    int orig = (i < N) ? g_degi_i[i] : 0;
    int v = orig;
    __shared__ int wsum[32];
    int w = threadIdx.x >> 5, l = threadIdx.x & 31;
#pragma unroll
    for (int o = 1; o < 32; o <<= 1) {          // warp inclusive scan
        int t = __shfl_up_sync(~0u, v, o);
        if (l >= o) v += t;
    }
    if (l == 31) wsum[w] = v;
    __syncthreads();
    if (w == 0) {
        int s = wsum[l];
#pragma unroll
        for (int o = 1; o < 32; o <<= 1) {
            int t = __shfl_up_sync(~0u, s, o);
            if (l >= o) s += t;
        }
        wsum[l] = s;
    }
    __syncthreads();
    int incl = v + (w ? wsum[w - 1] : 0);
    int excl = incl - orig + g_part[blockIdx.x];
    if (i < N) {
        g_rowptr[i] = excl;
        g_cursor[i] = excl;
        int d0 = g_dego_i[i];
        g_no[i] = d0 > 0 ? rsqrtf((float)d0) : 0.f;
        g_ni[i] = orig > 0 ? rsqrtf((float)orig) : 0.f;
    }
}

__global__ void k_bin(const int* __restrict__ src, const int* __restrict__ dst, int E) {
    int e = blockIdx.x * blockDim.x + threadIdx.x;
    if (e >= E) return;
    int pos = atomicAdd(&g_cursor[dst[e]], 1);
    g_eidx[pos] = src[e];
}

// ---- h = x * norm_out : 4 float4s / thread, one norm load amortized ----
__global__ void k_scale(const float4* __restrict__ x, int N) {
    int t = blockIdx.x * blockDim.x + threadIdx.x;
    if (t >= N * 4) return;
    int row = t >> 2;
    float s = g_no[row];
    int base = row * 16 + (t & 3) * 4;
#pragma unroll
    for (int i = 0; i < 4; i++) {
        float4 v = __ldg(x + base + i);
        v.x *= s; v.y *= s; v.z *= s; v.w *= s;
        g_h[base + i] = v;
    }
}

// ---- pull aggregation: one half-warp (16 lanes) per dst node, 4-edge unroll ----
template<int L>
__global__ void __launch_bounds__(256) k_gather(int N) {
    int hw = (blockIdx.x * 256 + threadIdx.x) >> 4;
    if (hw >= N) return;
    int lane = threadIdx.x & 15;
    const float4* __restrict__ h   = L ? g_y : g_h;
    float4*       __restrict__ agg = L ? g_agg2 : g_agg1;
    int start = g_rowptr[hw];
    int deg   = g_degi_i[hw];
    float4 a = make_float4(0.f, 0.f, 0.f, 0.f);
    int j = 0;
    for (; j + 4 <= deg; j += 4) {
        int s0 = __ldg(g_eidx + start + j);
        int s1 = __ldg(g_eidx + start + j + 1);
        int s2 = __ldg(g_eidx + start + j + 2);
        int s3 = __ldg(g_eidx + start + j + 3);
        float4 v0 = __ldg(h + s0 * 16 + lane);
        float4 v1 = __ldg(h + s1 * 16 + lane);
        float4 v2 = __ldg(h + s2 * 16 + lane);
        float4 v3 = __ldg(h + s3 * 16 + lane);
        a.x += (v0.x + v1.x) + (v2.x + v3.x);
        a.y += (v0.y + v1.y) + (v2.y + v3.y);
        a.z += (v0.z + v1.z) + (v2.z + v3.z);
        a.w += (v0.w + v1.w) + (v2.w + v3.w);
    }
    for (; j < deg; j++) {
        int s = __ldg(g_eidx + start + j);
        float4 v = __ldg(h + s * 16 + lane);
        a.x += v.x; a.y += v.y; a.z += v.z; a.w += v.w;
    }
    agg[hw * 16 + lane] = a;
}

// ---- 64-wide GEMM: out = f((agg * norm_in) @ W + b) ----
template<int MODE>
__global__ void __launch_bounds__(256, 4)
k_gemm(const float* __restrict__ W, const float* __restrict__ bias,
       float* __restrict__ dout, int N) {
    __shared__ float  As[64][65];
    __shared__ float4 Ws[64 * 16];
    int t  = threadIdx.x;
    int r0 = blockIdx.x * 64;
    const float4* __restrict__ A = (MODE == 0) ? g_agg1 : g_agg2;
    const float4* W4 = reinterpret_cast<const float4*>(W);

#pragma unroll
    for (int i = 0; i < 4; i++) Ws[t + 256 * i] = W4[t + 256 * i];
#pragma unroll
    for (int i = 0; i < 4; i++) {
        int f   = t + 256 * i;
        int row = f >> 4, c4 = f & 15;
        int gr  = r0 + row;
        float4 v = make_float4(0.f, 0.f, 0.f, 0.f);
        if (gr < N) {
            v = A[gr * 16 + c4];
            float ni = g_ni[gr];
            v.x *= ni; v.y *= ni; v.z *= ni; v.w *= ni;
        }
        As[row][c4 * 4 + 0] = v.x; As[row][c4 * 4 + 1] = v.y;
        As[row][c4 * 4 + 2] = v.z; As[row][c4 * 4 + 3] = v.w;
    }
    __syncthreads();

    int rr = (t >> 4) * 4;
    int cc = (t & 15) * 4;
    float acc[4][4];
#pragma unroll
    for (int i = 0; i < 4; i++)
#pragma unroll
        for (int j = 0; j < 4; j++) acc[i][j] = 0.f;

#pragma unroll
    for (int k = 0; k < 64; k++) {
        float4 w = Ws[k * 16 + (t & 15)];
#pragma unroll
        for (int i = 0; i < 4; i++) {
            float a = As[rr + i][k];
            acc[i][0] += a * w.x; acc[i][1] += a * w.y;
            acc[i][2] += a * w.z; acc[i][3] += a * w.w;
        }
    }

    float b0 = bias[cc], b1 = bias[cc + 1], b2 = bias[cc + 2], b3 = bias[cc + 3];
#pragma unroll
    for (int i = 0; i < 4; i++) {
        int gr = r0 + rr + i;
        if (gr >= N) continue;
        float v0 = acc[i][0] + b0, v1 = acc[i][1] + b1;
        float v2 = acc[i][2] + b2, v3 = acc[i][3] + b3;
        if (MODE == 0) {
            float no = g_no[gr];
            g_y[gr * 16 + (cc >> 2)] =
                make_float4(tanhf(v0) * no, tanhf(v1) * no,
                            tanhf(v2) * no, tanhf(v3) * no);
        } else {
            int   oc  = (cc + 32) & 63;
            float sgn = (cc < 32) ? -1.f : 1.f;
            reinterpret_cast<float4*>(dout)[gr * 16 + (oc >> 2)] =
                make_float4(sgn * v0, sgn * v1, sgn * v2, sgn * v3);
        }
    }
}

extern "C" void kernel_launch(void* const* d_in, const int* in_sizes, int n_in,
                              void* d_out, int out_size) {
    const float* x   = (const float*)d_in[0];
    const int*   src = (const int*)  d_in[1];
    const int*   dst = (const int*)  d_in[2];
    const float* W1  = (const float*)d_in[3];
    const float* b1  = (const float*)d_in[4];
    const float* W2  = (const float*)d_in[5];
    const float* b2  = (const float*)d_in[6];

    int N = in_sizes[0] / FEAT;   // 50000
    int E = in_sizes[1];          // 800000
    const int T = 256;
    int NB = (N + 1023) / 1024;

    k_zero<<<(N + 1023) / 1024, 1024>>>(N);
    k_deg<<<(E + T - 1) / T, T>>>(src, dst, E);
    k_scan_part<<<NB, 1024>>>(N);
    k_scan_mid<<<1, 32>>>(NB);
    k_scan_final<<<NB, 1024>>>(N);
    k_bin<<<(E + T - 1) / T, T>>>(src, dst, E);
    k_scale<<<(N * 4 + T - 1) / T, T>>>((const float4*)x, N);

    int gatherBlocks = (N * 16 + 255) / 256;
    int gemmBlocks   = (N + 63) / 64;

    k_gather<0><<<gatherBlocks, 256>>>(N);
    k_gemm<0><<<gemmBlocks, 256>>>(W1, b1, nullptr, N);
    k_gather<1><<<gatherBlocks, 256>>>(N);
    k_gemm<1><<<gemmBlocks, 256>>>(W2, b2, (float*)d_out, N);
}

// round 4
// speedup vs baseline: 1.3331x; 1.0198x over previous
#include <cuda_runtime.h>
#include <cuda_fp16.h>

#define MAXN 50048
#define MAXE 800000
#define FEAT 64

// ---- static device scratch ----
__device__ uint2  g_h[MAXN * 16];      // fp16 payload: 4 halves per entry, 64/row
__device__ uint2  g_y[MAXN * 16];      // fp16 payload
__device__ float4 g_agg1[MAXN * 16];
__device__ float4 g_agg2[MAXN * 16];
__device__ float  g_no[MAXN];          // D_src^{-1/2}
__device__ float  g_ni[MAXN];          // D_dst^{-1/2}
__device__ int    g_dego_i[MAXN];
__device__ int    g_degi_i[MAXN];
__device__ int    g_rowptr[MAXN];
__device__ int    g_cursor[MAXN];
__device__ int    g_part[128];
__device__ int    g_eidx[MAXE];        // CSR-by-dst: src ids

__global__ void k_zero(int N) {
    int i = blockIdx.x * blockDim.x + threadIdx.x;
    if (i < N) { g_dego_i[i] = 0; g_degi_i[i] = 0; }
}

__global__ void k_deg(const int* __restrict__ src, const int* __restrict__ dst, int E) {
    int e = blockIdx.x * blockDim.x + threadIdx.x;
    if (e >= E) return;
    atomicAdd(&g_dego_i[src[e]], 1);
    atomicAdd(&g_degi_i[dst[e]], 1);
}

// ---- 3-phase exclusive scan of degi -> rowptr (chunk = 1024) ----
__global__ void k_scan_part(int N) {
    int i = blockIdx.x * 1024 + threadIdx.x;
    int v = (i < N) ? g_degi_i[i] : 0;
    __shared__ int sh[32];
    int w = threadIdx.x >> 5, l = threadIdx.x & 31;
#pragma unroll
    for (int o = 16; o; o >>= 1) v += __shfl_down_sync(~0u, v, o);
    if (l == 0) sh[w] = v;
    __syncthreads();
    if (w == 0) {
        int s = sh[l];
#pragma unroll
        for (int o = 16; o; o >>= 1) s += __shfl_down_sync(~0u, s, o);
        if (l == 0) g_part[blockIdx.x] = s;
    }
}

// parallel exclusive scan of up to 64 block partials (one 64-thread block)
__global__ void k_scan_mid(int NB) {
    __shared__ int sh[64];
    int t = threadIdx.x;
    sh[t] = (t < NB) ? g_part[t] : 0;
    __syncthreads();
#pragma unroll
    for (int o = 1; o < 64; o <<= 1) {
        int v = (t >= o) ? sh[t - o] : 0;
        __syncthreads();
        sh[t] += v;
        __syncthreads();
    }
    if (t < NB) g_part[t] = (t == 0) ? 0 : sh[t - 1];
}

__global__ void k_scan_final(int N) {
    int i = blockIdx.x * 1024 + threadIdx.x;
    int orig = (i < N) ? g_degi_i[i] : 0;
    int v = orig;
    __shared__ int wsum[32];
    int w = threadIdx.x >> 5, l = threadIdx.x & 31;
#pragma unroll
    for (int o = 1; o < 32; o <<= 1) {
        int t = __shfl_up_sync(~0u, v, o);
        if (l >= o) v += t;
    }
    if (l == 31) wsum[w] = v;
    __syncthreads();
    if (w == 0) {
        int s = wsum[l];
#pragma unroll
        for (int o = 1; o < 32; o <<= 1) {
            int t = __shfl_up_sync(~0u, s, o);
            if (l >= o) s += t;
        }
        wsum[l] = s;
    }
    __syncthreads();
    int incl = v + (w ? wsum[w - 1] : 0);
    int excl = incl - orig + g_part[blockIdx.x];
    if (i < N) {
        g_rowptr[i] = excl;
        g_cursor[i] = excl;
        int d0 = g_dego_i[i];
        g_no[i] = d0 > 0 ? rsqrtf((float)d0) : 0.f;
        g_ni[i] = orig > 0 ? rsqrtf((float)orig) : 0.f;
    }
}

__global__ void k_bin(const int* __restrict__ src, const int* __restrict__ dst, int E) {
    int e = blockIdx.x * blockDim.x + threadIdx.x;
    if (e >= E) return;
    int pos = atomicAdd(&g_cursor[dst[e]], 1);
    g_eidx[pos] = src[e];
}

__device__ __forceinline__ uint2 pack4(float a, float b, float c, float d) {
    __half2 lo = __floats2half2_rn(a, b);
    __half2 hi = __floats2half2_rn(c, d);
    uint2 r;
    r.x = *reinterpret_cast<unsigned int*>(&lo);
    r.y = *reinterpret_cast<unsigned int*>(&hi);
    return r;
}

// ---- h = (x * norm_out) as fp16 : one float4 in, one uint2 out ----
__global__ void k_scale(const float4* __restrict__ x, int N) {
    int t = blockIdx.x * blockDim.x + threadIdx.x;
    if (t >= N * 4) return;
    int row = t >> 2;
    float s = g_no[row];
    int base = row * 16 + (t & 3) * 4;
#pragma unroll
    for (int i = 0; i < 4; i++) {
        float4 v = __ldg(x + base + i);
        g_h[base + i] = pack4(v.x * s, v.y * s, v.z * s, v.w * s);
    }
}

__device__ __forceinline__ void acc4(float4& a, uint2 p) {
    __half2 lo = *reinterpret_cast<__half2*>(&p.x);
    __half2 hi = *reinterpret_cast<__half2*>(&p.y);
    a.x += __low2float(lo); a.y += __high2float(lo);
    a.z += __low2float(hi); a.w += __high2float(hi);
}

// ---- pull aggregation: one half-warp per dst node, fp16 payload, 4-edge unroll ----
template<int L>
__global__ void __launch_bounds__(256) k_gather(int N) {
    int hw = (blockIdx.x * 256 + threadIdx.x) >> 4;
    if (hw >= N) return;
    int lane = threadIdx.x & 15;
    const uint2* __restrict__ h   = L ? g_y : g_h;
    float4*      __restrict__ agg = L ? g_agg2 : g_agg1;
    int start = g_rowptr[hw];
    int deg   = g_degi_i[hw];
    float4 a = make_float4(0.f, 0.f, 0.f, 0.f);
    int j = 0;
    for (; j + 4 <= deg; j += 4) {
        int s0 = __ldg(g_eidx + start + j);
        int s1 = __ldg(g_eidx + start + j + 1);
        int s2 = __ldg(g_eidx + start + j + 2);
        int s3 = __ldg(g_eidx + start + j + 3);
        uint2 v0 = __ldg(h + s0 * 16 + lane);
        uint2 v1 = __ldg(h + s1 * 16 + lane);
        uint2 v2 = __ldg(h + s2 * 16 + lane);
        uint2 v3 = __ldg(h + s3 * 16 + lane);
        acc4(a, v0); acc4(a, v1); acc4(a, v2); acc4(a, v3);
    }
    for (; j < deg; j++) {
        int s = __ldg(g_eidx + start + j);
        uint2 v = __ldg(h + s * 16 + lane);
        acc4(a, v);
    }
    agg[hw * 16 + lane] = a;
}

// ---- 64-wide GEMM: out = f((agg * norm_in) @ W + b) ----
template<int MODE>
__global__ void __launch_bounds__(256, 4)
k_gemm(const float* __restrict__ W, const float* __restrict__ bias,
       float* __restrict__ dout, int N) {
    __shared__ float  As[64][65];
    __shared__ float4 Ws[64 * 16];
    int t  = threadIdx.x;
    int r0 = blockIdx.x * 64;
    const float4* __restrict__ A = (MODE == 0) ? g_agg1 : g_agg2;
    const float4* W4 = reinterpret_cast<const float4*>(W);

#pragma unroll
    for (int i = 0; i < 4; i++) Ws[t + 256 * i] = W4[t + 256 * i];
#pragma unroll
    for (int i = 0; i < 4; i++) {
        int f   = t + 256 * i;
        int row = f >> 4, c4 = f & 15;
        int gr  = r0 + row;
        float4 v = make_float4(0.f, 0.f, 0.f, 0.f);
        if (gr < N) {
            v = A[gr * 16 + c4];
            float ni = g_ni[gr];
            v.x *= ni; v.y *= ni; v.z *= ni; v.w *= ni;
        }
        As[row][c4 * 4 + 0] = v.x; As[row][c4 * 4 + 1] = v.y;
        As[row][c4 * 4 + 2] = v.z; As[row][c4 * 4 + 3] = v.w;
    }
    __syncthreads();

    int rr = (t >> 4) * 4;
    int cc = (t & 15) * 4;
    float acc[4][4];
#pragma unroll
    for (int i = 0; i < 4; i++)
#pragma unroll
        for (int j = 0; j < 4; j++) acc[i][j] = 0.f;

#pragma unroll
    for (int k = 0; k < 64; k++) {
        float4 w = Ws[k * 16 + (t & 15)];
#pragma unroll
        for (int i = 0; i < 4; i++) {
            float a = As[rr + i][k];
            acc[i][0] += a * w.x; acc[i][1] += a * w.y;
            acc[i][2] += a * w.z; acc[i][3] += a * w.w;
        }
    }

    float b0 = bias[cc], b1 = bias[cc + 1], b2 = bias[cc + 2], b3 = bias[cc + 3];
#pragma unroll
    for (int i = 0; i < 4; i++) {
        int gr = r0 + rr + i;
        if (gr >= N) continue;
        float v0 = acc[i][0] + b0, v1 = acc[i][1] + b1;
        float v2 = acc[i][2] + b2, v3 = acc[i][3] + b3;
        if (MODE == 0) {
            float no = g_no[gr];
            g_y[gr * 16 + (cc >> 2)] =
                pack4(tanhf(v0) * no, tanhf(v1) * no, tanhf(v2) * no, tanhf(v3) * no);
        } else {
            int   oc  = (cc + 32) & 63;
            float sgn = (cc < 32) ? -1.f : 1.f;
            reinterpret_cast<float4*>(dout)[gr * 16 + (oc >> 2)] =
                make_float4(sgn * v0, sgn * v1, sgn * v2, sgn * v3);
        }
    }
}

extern "C" void kernel_launch(void* const* d_in, const int* in_sizes, int n_in,
                              void* d_out, int out_size) {
    const float* x   = (const float*)d_in[0];
    const int*   src = (const int*)  d_in[1];
    const int*   dst = (const int*)  d_in[2];
    const float* W1  = (const float*)d_in[3];
    const float* b1  = (const float*)d_in[4];
    const float* W2  = (const float*)d_in[5];
    const float* b2  = (const float*)d_in[6];

    int N = in_sizes[0] / FEAT;   // 50000
    int E = in_sizes[1];          // 800000
    const int T = 256;
    int NB = (N + 1023) / 1024;

    k_zero<<<(N + 1023) / 1024, 1024>>>(N);
    k_deg<<<(E + T - 1) / T, T>>>(src, dst, E);
    k_scan_part<<<NB, 1024>>>(N);
    k_scan_mid<<<1, 64>>>(NB);
    k_scan_final<<<NB, 1024>>>(N);
    k_bin<<<(E + T - 1) / T, T>>>(src, dst, E);
    k_scale<<<(N * 4 + T - 1) / T, T>>>((const float4*)x, N);

    int gatherBlocks = (N * 16 + 255) / 256;
    int gemmBlocks   = (N + 63) / 64;

    k_gather<0><<<gatherBlocks, 256>>>(N);
    k_gemm<0><<<gemmBlocks, 256>>>(W1, b1, nullptr, N);
    k_gather<1><<<gatherBlocks, 256>>>(N);
    k_gemm<1><<<gemmBlocks, 256>>>(W2, b2, (float*)d_out, N);
}